// round 11
// baseline (speedup 1.0000x reference)
#include <cuda_runtime.h>
#include <math.h>
#include <stdint.h>

#define Bz 32
#define Tz 1024
#define Dz 256
#define Hz 256
#define NG 1024  // 4*H

// ---------------- scratch (device globals: no allocation allowed) ----------
__device__ __align__(16) float g_xp1[2][Tz][Bz][NG];   // layer1 gate preacts
__device__ __align__(16) float g_xp2[2][Tz][Bz][NG];   // layer2 gate preacts
__device__ __align__(16) float g_h1 [2][Tz][Bz][Hz];   // layer1 hidden states (orig-time)
__device__ __align__(16) float g_Wt[6][1024][256];     // transposed weights [n][k] (tf32-rounded)

// ---------------- helpers ----------------------------------------------------
__device__ __forceinline__ float fast_tanh(float x) {
    float t;
    asm("tanh.approx.f32 %0, %1;" : "=f"(t) : "f"(x));
    return t;
}
__device__ __forceinline__ float fast_sigmoid(float x) {
    return fmaf(fast_tanh(0.5f * x), 0.5f, 0.5f);
}
__device__ __forceinline__ uint32_t f2tf32(float f) {
    uint32_t u;
    asm("cvt.rna.tf32.f32 %0, %1;" : "=r"(u) : "f"(f));
    return u;
}
__device__ __forceinline__ void mma_tf32(float* d, const uint32_t* a, const uint32_t* b) {
    asm volatile(
        "mma.sync.aligned.m16n8k8.row.col.f32.tf32.tf32.f32 "
        "{%0,%1,%2,%3}, {%4,%5,%6,%7}, {%8,%9}, {%0,%1,%2,%3};"
        : "+f"(d[0]), "+f"(d[1]), "+f"(d[2]), "+f"(d[3])
        : "r"(a[0]), "r"(a[1]), "r"(a[2]), "r"(a[3]), "r"(b[0]), "r"(b[1]));
}
__device__ __forceinline__ uint32_t smem_u32(const void* p) {
    uint32_t a;
    asm("{ .reg .u64 t; cvta.to.shared.u64 t, %1; cvt.u32.u64 %0, t; }" : "=r"(a) : "l"(p));
    return a;
}
__device__ __forceinline__ uint32_t cluster_rank() {
    uint32_t r;
    asm("mov.u32 %0, %%cluster_ctarank;" : "=r"(r));
    return r;
}
__device__ __forceinline__ uint32_t mapa_u32(uint32_t local, uint32_t rank) {
    uint32_t ra;
    asm("mapa.shared::cluster.u32 %0, %1, %2;" : "=r"(ra) : "r"(local), "r"(rank));
    return ra;
}
__device__ __forceinline__ void st_async_u32(uint32_t dst, uint32_t v, uint32_t mbar) {
    asm volatile("st.async.shared::cluster.mbarrier::complete_tx::bytes.b32 [%0], %1, [%2];"
                 :: "r"(dst), "r"(v), "r"(mbar) : "memory");
}
#define MBARRIER_INIT(mb, cnt) \
    asm volatile("mbarrier.init.shared.b64 [%0], %1;" :: "r"((uint32_t)(mb)), "r"((uint32_t)(cnt)) : "memory")
#define MBARRIER_ARRIVE_EXPECT_TX(mb, bytes) \
    asm volatile("mbarrier.arrive.expect_tx.shared.b64 _, [%0], %1;" \
        :: "r"((uint32_t)(mb)), "r"((uint32_t)(bytes)) : "memory")
#define MBAR_WAIT(mb, ph) do { \
    uint32_t _m = (uint32_t)(mb); uint32_t _p = (uint32_t)(ph); uint32_t _d; \
    asm volatile("{ .reg .pred p; mbarrier.try_wait.parity.acquire.cta.shared::cta.b64 p, [%1], %2; selp.b32 %0,1,0,p; }" \
        : "=r"(_d) : "r"(_m), "r"(_p) : "memory"); \
    if (!_d) { \
        asm volatile("{ .reg .pred P1;\nWL_%=:\n mbarrier.try_wait.parity.acquire.cta.shared::cta.b64 P1, [%0], %1, 0x989680;\n @P1 bra.uni WD_%=;\n bra.uni WL_%=;\nWD_%=:\n}" \
            :: "r"(_m), "r"(_p) : "memory"); \
    } \
} while (0)
#define CLUSTER_SYNC() do { \
    asm volatile("barrier.cluster.arrive.aligned;" ::: "memory"); \
    asm volatile("barrier.cluster.wait.aligned;" ::: "memory"); \
} while (0)

// fragment-order h layout: row = n*4 + (k&3), entry = k>>2, row stride 68 floats
#define HP_STR 68
#define HP_BUF (16 * HP_STR)      // floats per buffer
#define TXB1 4096u

// ---------------- weight transpose (stores tf32-rounded values) --------------
__global__ void k_transpose(const float* W0, const float* W1, const float* W2,
                            const float* W3, const float* W4, const float* W5) {
    int z = blockIdx.z;
    int tsr = z >> 2, g = z & 3;
    const float* W;
    switch (tsr) {
        case 0: W = W0; break; case 1: W = W1; break; case 2: W = W2; break;
        case 3: W = W3; break; case 4: W = W4; break; default: W = W5; break;
    }
    __shared__ float tile[32][33];
    int h0 = blockIdx.x * 32, d0 = blockIdx.y * 32;
    int tx = threadIdx.x, ty = threadIdx.y;
#pragma unroll
    for (int i = 0; i < 4; ++i) {
        int r = ty + i * 8;
        tile[r][tx] = W[(size_t)g * 65536 + (size_t)(d0 + r) * 256 + h0 + tx];
    }
    __syncthreads();
    float* out = &g_Wt[tsr][0][0];
#pragma unroll
    for (int i = 0; i < 4; ++i) {
        int r = ty + i * 8;
        out[(size_t)(g * 256 + h0 + r) * 256 + d0 + tx] =
            __uint_as_float(f2tf32(tile[tx][r]));
    }
}

// ---------------- tensor-core GEMM via mma.sync tf32 (unchanged) -------------
#define KS 36
__global__ void __launch_bounds__(256, 2) k_gemm_mma(
    const float* __restrict__ x,
    const float* __restrict__ bias0, const float* __restrict__ bias1,
    int layer)
{
    __shared__ uint32_t As[128 * KS];
    __shared__ uint32_t Bs[128 * KS];

    const int dir = blockIdx.z;
    const int m0 = blockIdx.y * 128, n0 = blockIdx.x * 128;
    const float* hsrc = &g_h1[dir][0][0][0];
    float* out = (layer == 1) ? &g_xp1[dir][0][0][0] : &g_xp2[dir][0][0][0];
    const float* bias = dir ? bias1 : bias0;
    const float* WtX = &g_Wt[(layer == 1) ? dir : 2 + dir][0][0];
    const float* WtH = &g_Wt[4 + dir][0][0];
    const int NC = (layer == 1) ? 8 : 16;

    const int tid = threadIdx.x, wid = tid >> 5, lane = tid & 31;
    const int wm = (wid >> 2) * 64;
    const int wn = (wid & 3) * 32;
    const int kq = lane & 3, rq = lane >> 2;

    float acc[4][4][4];
#pragma unroll
    for (int mf = 0; mf < 4; ++mf)
#pragma unroll
        for (int nf = 0; nf < 4; ++nf)
#pragma unroll
            for (int r = 0; r < 4; ++r) acc[mf][nf][r] = 0.f;

    const int lrow = tid >> 3;
    const int lk4  = (tid & 7) * 4;

    for (int c = 0; c < NC; ++c) {
        const bool isH = (c >= 8);
        const int kc = (c & 7) * 32;
        const float* Wt = isH ? WtH : WtX;

#pragma unroll
        for (int i = 0; i < 4; ++i) {
            int row = lrow + i * 32;
            int m = m0 + row, t = m >> 5, bb = m & 31;
            int tt = dir ? (Tz - 1 - t) : t;
            const float* ap = isH ? hsrc + ((size_t)tt * 32 + bb) * 256 + kc + lk4
                                  : x + ((size_t)bb * Tz + tt) * 256 + kc + lk4;
            float4 v = *(const float4*)ap;
            uint4 u = make_uint4(f2tf32(v.x), f2tf32(v.y), f2tf32(v.z), f2tf32(v.w));
            *(uint4*)&As[row * KS + lk4] = u;
        }
#pragma unroll
        for (int i = 0; i < 4; ++i) {
            int nr = lrow + i * 32;
            float4 v = *(const float4*)(Wt + (size_t)(n0 + nr) * 256 + kc + lk4);
            uint4 u = make_uint4(__float_as_uint(v.x), __float_as_uint(v.y),
                                 __float_as_uint(v.z), __float_as_uint(v.w));
            *(uint4*)&Bs[nr * KS + lk4] = u;
        }
        __syncthreads();

#pragma unroll
        for (int ks = 0; ks < 4; ++ks) {
            const int kk = ks * 8 + kq;
            uint32_t a[4][4], b[4][2];
#pragma unroll
            for (int mf = 0; mf < 4; ++mf) {
                int mi = wm + mf * 16 + rq;
                a[mf][0] = As[mi * KS + kk];
                a[mf][1] = As[(mi + 8) * KS + kk];
                a[mf][2] = As[mi * KS + kk + 4];
                a[mf][3] = As[(mi + 8) * KS + kk + 4];
            }
#pragma unroll
            for (int nf = 0; nf < 4; ++nf) {
                int ni = wn + nf * 8 + rq;
                b[nf][0] = Bs[ni * KS + kk];
                b[nf][1] = Bs[ni * KS + kk + 4];
            }
#pragma unroll
            for (int mf = 0; mf < 4; ++mf)
#pragma unroll
                for (int nf = 0; nf < 4; ++nf)
                    mma_tf32(acc[mf][nf], a[mf], b[nf]);
        }
        __syncthreads();
    }

#pragma unroll
    for (int nf = 0; nf < 4; ++nf) {
        int n = n0 + wn + nf * 8 + 2 * kq;
        float bx = 0.f, by = 0.f;
        if (layer == 1) { bx = bias[n]; by = bias[n + 1]; }
#pragma unroll
        for (int mf = 0; mf < 4; ++mf) {
            int m = m0 + wm + mf * 16 + rq;
            float2 v0 = make_float2(acc[mf][nf][0] + bx, acc[mf][nf][1] + by);
            float2 v1 = make_float2(acc[mf][nf][2] + bx, acc[mf][nf][3] + by);
            *(float2*)&out[(size_t)m * NG + n]       = v0;
            *(float2*)&out[(size_t)(m + 8) * NG + n] = v1;
        }
    }
}

// ---------------- layer1 recurrence: tensor core + frag-order h, 1 sync/step -
__global__ void __launch_bounds__(256, 1) __cluster_dims__(8, 1, 1)
k_recur1(const float* __restrict__ Uf, const float* __restrict__ Ub)
{
    __shared__ __align__(16) uint32_t sHp[2 * HP_BUF];  // tf32 bits, frag order
    __shared__ float sGate[2][128 * 5];                 // double-buffered [gc][b]
    __shared__ __align__(8) unsigned long long mb1[2];

    const int cid = blockIdx.x >> 3;
    const int dir = cid >> 3;
    const int bg  = cid & 7;
    const int r   = (int)cluster_rank();

    const float* U  = dir ? Ub : Uf;
    const float* xp = &g_xp1[dir][0][0][0];
    float* hs = &g_h1[dir][0][0][0];

    const uint32_t shp_base = smem_u32(&sHp[0]);
    const uint32_t mb_base  = smem_u32(&mb1[0]);

    const int tid = threadIdx.x, lane = tid & 31, w = tid >> 5;
    const int rq = lane >> 2, kq = lane & 3;

    // static A fragments: gc = w*16 + rq (+8), A[m][k] = U[g][k][r*32+hcol]
    const int gc0 = w * 16 + rq, gc1 = gc0 + 8;
    const int gg0 = gc0 >> 5, gg1 = gc1 >> 5;
    const int colu0 = r * 32 + (gc0 & 31), colu1 = r * 32 + (gc1 & 31);
    uint32_t ua[32][4];
#pragma unroll
    for (int kt = 0; kt < 32; ++kt) {
        int k0 = kt * 8 + kq;
        ua[kt][0] = f2tf32(U[(size_t)gg0 * 65536 + (size_t)k0 * 256 + colu0]);
        ua[kt][1] = f2tf32(U[(size_t)gg1 * 65536 + (size_t)k0 * 256 + colu1]);
        ua[kt][2] = f2tf32(U[(size_t)gg0 * 65536 + (size_t)(k0 + 4) * 256 + colu0]);
        ua[kt][3] = f2tf32(U[(size_t)gg1 * 65536 + (size_t)(k0 + 4) * 256 + colu1]);
    }

    for (int i = tid; i < 2 * HP_BUF; i += 256) sHp[i] = 0u;
    if (tid == 0) {
        MBARRIER_INIT(mb_base, 1);
        MBARRIER_INIT(mb_base + 8, 1);
        MBARRIER_ARRIVE_EXPECT_TX(mb_base, TXB1);
        MBARRIER_ARRIVE_EXPECT_TX(mb_base + 8, TXB1);
    }
    __syncthreads();
    CLUSTER_SYNC();

    const int cb = tid >> 5, chl = tid & 31;     // cell role (tid<128): batch=cb
    const int col = r * 32 + chl;
    const int bglob = bg * 4 + cb;
    const uint32_t hoff_cell = shp_base +
        (((cb * 4 + (col & 3)) * HP_STR + (col >> 2)) * 4);

    float c_state = 0.f;
    float xq[4] = {0.f, 0.f, 0.f, 0.f};
    if (tid < 128) {
        size_t xb = (size_t)bglob * NG + col;
        xq[0] = xp[xb]; xq[1] = xp[xb + 256]; xq[2] = xp[xb + 512]; xq[3] = xp[xb + 768];
    }
    int pp[2] = {0, 0};

    const uint4* hrow4_0 = (const uint4*)&sHp[((rq & 3) * 4 + kq) * HP_STR];
    const uint4* hrow4_1 = (const uint4*)&sHp[HP_BUF + ((rq & 3) * 4 + kq) * HP_STR];

    for (int t = 0; t < Tz; ++t) {
        float xn[4] = {0.f, 0.f, 0.f, 0.f};
        if (tid < 128 && t + 1 < Tz) {
            size_t xb = ((size_t)(t + 1) * 32 + bglob) * NG + col;
            xn[0] = xp[xb]; xn[1] = xp[xb + 256]; xn[2] = xp[xb + 512]; xn[3] = xp[xb + 768];
        }
        const int bs = t & 1;
        if (t > 0) {
            MBAR_WAIT(mb_base + bs * 8, pp[bs]);
            pp[bs] ^= 1;
        }
        if (t > 0 && tid == 0)
            MBARRIER_ARRIVE_EXPECT_TX(mb_base + bs * 8, TXB1);

        const uint4* hr = bs ? hrow4_1 : hrow4_0;
        float acc[4][4];
#pragma unroll
        for (int j = 0; j < 4; ++j)
#pragma unroll
            for (int q = 0; q < 4; ++q) acc[j][q] = 0.f;
#pragma unroll
        for (int j = 0; j < 16; ++j) {
            uint4 hv = hr[j];
            uint32_t b0[2] = {hv.x, hv.y};
            uint32_t b1[2] = {hv.z, hv.w};
            mma_tf32(acc[(2 * j) & 3], ua[2 * j], b0);
            mma_tf32(acc[(2 * j + 1) & 3], ua[2 * j + 1], b1);
        }
        float c0 = acc[0][0] + acc[1][0] + acc[2][0] + acc[3][0];
        float c1 = acc[0][1] + acc[1][1] + acc[2][1] + acc[3][1];
        float c2 = acc[0][2] + acc[1][2] + acc[2][2] + acc[3][2];
        float c3 = acc[0][3] + acc[1][3] + acc[2][3] + acc[3][3];
        float* sg = sGate[bs];
        if (kq < 2) {
            sg[gc0 * 5 + 2 * kq]     = c0;
            sg[gc0 * 5 + 2 * kq + 1] = c1;
            sg[gc1 * 5 + 2 * kq]     = c2;
            sg[gc1 * 5 + 2 * kq + 1] = c3;
        }
        __syncthreads();

        if (tid < 128) {
            float gi = fast_sigmoid(xq[0] + sg[(0  + chl) * 5 + cb]);
            float gf = fast_sigmoid(xq[1] + sg[(32 + chl) * 5 + cb]);
            float gg = fast_sigmoid(xq[2] + sg[(64 + chl) * 5 + cb]);
            float go = fast_sigmoid(xq[3] + sg[(96 + chl) * 5 + cb]);
            c_state = gf + c_state + gi * gg;
            float hn = go + fast_tanh(c_state);
            int tout = dir ? (Tz - 1 - t) : t;
            hs[((size_t)tout * 32 + bglob) * 256 + col] = hn;
            if (t + 1 < Tz) {
                uint32_t ht = f2tf32(hn);
                uint32_t ho = hoff_cell + (((t + 1) & 1) ? HP_BUF * 4 : 0);
                uint32_t mbn = mb_base + ((t + 1) & 1) * 8;
#pragma unroll
                for (int j = 0; j < 8; ++j)
                    st_async_u32(mapa_u32(ho, (uint32_t)j), ht, mapa_u32(mbn, (uint32_t)j));
                xq[0] = xn[0]; xq[1] = xn[1]; xq[2] = xn[2]; xq[3] = xn[3];
            }
        }
        // no trailing sync: sGate double-buffered; sHp WAR ordered by mbarrier chain
    }
    CLUSTER_SYNC();
}

// ---------------- layer2 recurrence: cluster-2, warp-autonomous --------------
// CTA owns 128 cols x 4 batches; U[0] A-frags in regs; warp holds ALL k for its
// 16 cols -> cell update directly from MMA accumulators. No __syncthreads.
__global__ void __launch_bounds__(256, 1) __cluster_dims__(2, 1, 1)
k_recur2(const float* __restrict__ Uf, const float* __restrict__ Ub,
         const float* __restrict__ b2f, const float* __restrict__ b2b,
         float* __restrict__ dout)
{
    __shared__ __align__(16) uint32_t sHp2[2 * HP_BUF];
    __shared__ __align__(8) unsigned long long mb2[2];

    const int cid = blockIdx.x >> 1;
    const int dir = cid >> 3;
    const int bg  = cid & 7;
    const int rr  = (int)cluster_rank();

    const float* U  = dir ? Ub : Uf;      // only U[0] slice used
    const float* b2 = dir ? b2b : b2f;    // only b[0] used
    const float* xp = &g_xp2[dir][0][0][0];
    float* ynet = dout + (size_t)Bz * 512;
    float* yt   = dout;

    const uint32_t shp_base = smem_u32(&sHp2[0]);
    const uint32_t mb_base  = smem_u32(&mb2[0]);

    const int tid = threadIdx.x, lane = tid & 31, w = tid >> 5;
    const int rq = lane >> 2, kq = lane & 3;

    const int col0 = rr * 128 + w * 16 + rq;   // warp's 16 cols: col0, col0+8
    const int col1 = col0 + 8;

    // static A fragments from U[0]: m=rq -> col0, m=rq+8 -> col1; k = kt*8+kq(+4)
    uint32_t ua2[32][4];
#pragma unroll
    for (int kt = 0; kt < 32; ++kt) {
        int k0 = kt * 8 + kq;
        ua2[kt][0] = f2tf32(U[(size_t)k0 * 256 + col0]);
        ua2[kt][1] = f2tf32(U[(size_t)k0 * 256 + col1]);
        ua2[kt][2] = f2tf32(U[(size_t)(k0 + 4) * 256 + col0]);
        ua2[kt][3] = f2tf32(U[(size_t)(k0 + 4) * 256 + col1]);
    }

    for (int i = tid; i < 2 * HP_BUF; i += 256) sHp2[i] = 0u;
    if (tid == 0) {
        MBARRIER_INIT(mb_base, 8);       // one arrive per warp
        MBARRIER_INIT(mb_base + 8, 8);
    }
    __syncthreads();
    if (lane == 0) {
        MBARRIER_ARRIVE_EXPECT_TX(mb_base, 512u);
        MBARRIER_ARRIVE_EXPECT_TX(mb_base + 8, 512u);
    }
    CLUSTER_SYNC();

    const bool owner = (kq < 2);
    const int b0g = bg * 4 + 2 * kq, b1g = b0g + 1;   // valid when owner
    const float biasA = b2[col0 & 255], biasB = b2[col1 & 255];
    float cs[4] = {0.f, 0.f, 0.f, 0.f};
    // cells: 0:(col0,b0g) 1:(col0,b1g) 2:(col1,b0g) 3:(col1,b1g)
    float xq[16];
    if (owner) {
#pragma unroll
        for (int g = 0; g < 4; ++g) {
            xq[0 * 4 + g] = xp[(size_t)b0g * NG + g * 256 + (col0 & 255)];
            xq[1 * 4 + g] = xp[(size_t)b1g * NG + g * 256 + (col0 & 255)];
            xq[2 * 4 + g] = xp[(size_t)b0g * NG + g * 256 + (col1 & 255)];
            xq[3 * 4 + g] = xp[(size_t)b1g * NG + g * 256 + (col1 & 255)];
        }
    }
    const uint4* hrow4_0 = (const uint4*)&sHp2[((rq & 3) * 4 + kq) * HP_STR];
    const uint4* hrow4_1 = (const uint4*)&sHp2[HP_BUF + ((rq & 3) * 4 + kq) * HP_STR];
    int pp[2] = {0, 0};

    const int colA = col0 & 255, colB = col1 & 255;   // 0..255 output col idx
    const uint32_t hoA = shp_base + (((2 * kq * 4 + (colA & 3)) * HP_STR + (colA >> 2)) * 4);
    const uint32_t hoA1 = shp_base + ((((2 * kq + 1) * 4 + (colA & 3)) * HP_STR + (colA >> 2)) * 4);
    const uint32_t hoB = shp_base + (((2 * kq * 4 + (colB & 3)) * HP_STR + (colB >> 2)) * 4);
    const uint32_t hoB1 = shp_base + ((((2 * kq + 1) * 4 + (colB & 3)) * HP_STR + (colB >> 2)) * 4);

    for (int t = 0; t < Tz; ++t) {
        const int bs = t & 1;
        if (t > 0) {
            MBAR_WAIT(mb_base + bs * 8, pp[bs]);
            pp[bs] ^= 1;
            if (lane == 0)
                MBARRIER_ARRIVE_EXPECT_TX(mb_base + bs * 8, 512u);
        }
        const uint4* hr = bs ? hrow4_1 : hrow4_0;
        float acc[4][4];
#pragma unroll
        for (int j = 0; j < 4; ++j)
#pragma unroll
            for (int q = 0; q < 4; ++q) acc[j][q] = 0.f;
#pragma unroll
        for (int j = 0; j < 16; ++j) {
            uint4 hv = hr[j];
            uint32_t bf0[2] = {hv.x, hv.y};
            uint32_t bf1[2] = {hv.z, hv.w};
            mma_tf32(acc[(2 * j) & 3], ua2[2 * j], bf0);
            mma_tf32(acc[(2 * j + 1) & 3], ua2[2 * j + 1], bf1);
        }
        if (owner) {
            float hu[4];
            hu[0] = acc[0][0] + acc[1][0] + acc[2][0] + acc[3][0] + biasA;
            hu[1] = acc[0][1] + acc[1][1] + acc[2][1] + acc[3][1] + biasA;
            hu[2] = acc[0][2] + acc[1][2] + acc[2][2] + acc[3][2] + biasB;
            hu[3] = acc[0][3] + acc[1][3] + acc[2][3] + acc[3][3] + biasB;
            const int tt = dir ? (Tz - 1 - t) : t;
            const int nb = (t + 1) & 1;
            const uint32_t bufo = nb ? HP_BUF * 4 : 0;
            const uint32_t mbn = mb_base + nb * 8;
            const int bcell[4] = {b0g, b1g, b0g, b1g};
            const int ccell[4] = {colA, colA, colB, colB};
            const uint32_t hcell[4] = {hoA, hoA1, hoB, hoB1};
#pragma unroll
            for (int cc = 0; cc < 4; ++cc) {
                float gi = fast_sigmoid(xq[cc * 4 + 0] + hu[cc]);
                float gf = fast_sigmoid(xq[cc * 4 + 1] + hu[cc]);
                float gg = fast_sigmoid(xq[cc * 4 + 2] + hu[cc]);
                float go = fast_sigmoid(xq[cc * 4 + 3] + hu[cc]);
                cs[cc] = gf + cs[cc] + gi * gg;
                float hn = go + fast_tanh(cs[cc]);
                ynet[((size_t)bcell[cc] * Tz + tt) * 512 + dir * 256 + ccell[cc]] = hn;
                if (t == Tz - 1)
                    yt[(size_t)bcell[cc] * 512 + dir * 256 + ccell[cc]] = hn;
                if (t + 1 < Tz) {
                    uint32_t ht = f2tf32(hn);
                    st_async_u32(mapa_u32(hcell[cc] + bufo, 0u), ht, mapa_u32(mbn, 0u));
                    st_async_u32(mapa_u32(hcell[cc] + bufo, 1u), ht, mapa_u32(mbn, 1u));
                }
            }
            // late prefetch of xq for t+1 (hidden under next wait+MMA)
            if (t + 1 < Tz) {
                size_t tb = (size_t)(t + 1) * 32;
#pragma unroll
                for (int g = 0; g < 4; ++g) {
                    xq[0 * 4 + g] = xp[(tb + b0g) * NG + g * 256 + colA];
                    xq[1 * 4 + g] = xp[(tb + b1g) * NG + g * 256 + colA];
                    xq[2 * 4 + g] = xp[(tb + b0g) * NG + g * 256 + colB];
                    xq[3 * 4 + g] = xp[(tb + b1g) * NG + g * 256 + colB];
                }
            }
        }
    }
    CLUSTER_SYNC();
}

// ---------------- launch ------------------------------------------------------
extern "C" void kernel_launch(void* const* d_in, const int* in_sizes, int n_in,
                              void* d_out, int out_size) {
    const float* x      = (const float*)d_in[0];
    const float* l1_W   = (const float*)d_in[1];
    const float* l1_U   = (const float*)d_in[2];
    const float* l1_b   = (const float*)d_in[3];
    const float* l1_Wb  = (const float*)d_in[4];
    const float* l1_Ub  = (const float*)d_in[5];
    const float* l1_bb  = (const float*)d_in[6];
    const float* l2_Wx  = (const float*)d_in[7];
    const float* l2_Wh  = (const float*)d_in[8];
    const float* l2_U   = (const float*)d_in[9];
    const float* l2_b   = (const float*)d_in[10];
    const float* l2_Wxb = (const float*)d_in[11];
    const float* l2_Whb = (const float*)d_in[12];
    const float* l2_Ub  = (const float*)d_in[13];
    const float* l2_bb  = (const float*)d_in[14];
    float* out = (float*)d_out;

    dim3 tg(8, 8, 24);
    k_transpose<<<tg, dim3(32, 8)>>>(l1_W, l1_Wb, l2_Wx, l2_Wxb, l2_Wh, l2_Whb);

    dim3 gg(8, 256, 2);   // n-tiles, m-tiles, dir
    k_gemm_mma<<<gg, 256>>>(x, l1_b, l1_bb, 1);
    k_recur1<<<128, 256>>>(l1_U, l1_Ub);
    k_gemm_mma<<<gg, 256>>>(x, nullptr, nullptr, 2);
    k_recur2<<<32, 256>>>(l2_U, l2_Ub, l2_b, l2_bb, out);
}

// round 12
// speedup vs baseline: 1.0969x; 1.0969x over previous
#include <cuda_runtime.h>
#include <math.h>
#include <stdint.h>

#define Bz 32
#define Tz 1024
#define Dz 256
#define Hz 256
#define NG 1024  // 4*H

// ---------------- scratch (device globals: no allocation allowed) ----------
__device__ __align__(16) float g_xp1[2][Tz][Bz][NG];   // layer1 gate preacts
__device__ __align__(16) float g_xp2[2][Tz][Bz][NG];   // layer2 gate preacts
__device__ __align__(16) float g_h1 [2][Tz][Bz][Hz];   // layer1 hidden states (orig-time)
__device__ __align__(16) float g_Wt[6][1024][256];     // transposed weights [n][k] (tf32-rounded)

// ---------------- helpers ----------------------------------------------------
__device__ __forceinline__ float fast_tanh(float x) {
    float t;
    asm("tanh.approx.f32 %0, %1;" : "=f"(t) : "f"(x));
    return t;
}
__device__ __forceinline__ float fast_sigmoid(float x) {
    return fmaf(fast_tanh(0.5f * x), 0.5f, 0.5f);
}
__device__ __forceinline__ uint32_t f2tf32(float f) {
    uint32_t u;
    asm("cvt.rna.tf32.f32 %0, %1;" : "=r"(u) : "f"(f));
    return u;
}
__device__ __forceinline__ void mma_tf32(float* d, const uint32_t* a, const uint32_t* b) {
    asm volatile(
        "mma.sync.aligned.m16n8k8.row.col.f32.tf32.tf32.f32 "
        "{%0,%1,%2,%3}, {%4,%5,%6,%7}, {%8,%9}, {%0,%1,%2,%3};"
        : "+f"(d[0]), "+f"(d[1]), "+f"(d[2]), "+f"(d[3])
        : "r"(a[0]), "r"(a[1]), "r"(a[2]), "r"(a[3]), "r"(b[0]), "r"(b[1]));
}
__device__ __forceinline__ uint32_t smem_u32(const void* p) {
    uint32_t a;
    asm("{ .reg .u64 t; cvta.to.shared.u64 t, %1; cvt.u32.u64 %0, t; }" : "=r"(a) : "l"(p));
    return a;
}
__device__ __forceinline__ uint32_t cluster_rank() {
    uint32_t r;
    asm("mov.u32 %0, %%cluster_ctarank;" : "=r"(r));
    return r;
}
__device__ __forceinline__ uint32_t mapa_u32(uint32_t local, uint32_t rank) {
    uint32_t ra;
    asm("mapa.shared::cluster.u32 %0, %1, %2;" : "=r"(ra) : "r"(local), "r"(rank));
    return ra;
}
__device__ __forceinline__ void st_async_u32(uint32_t dst, uint32_t v, uint32_t mbar) {
    asm volatile("st.async.shared::cluster.mbarrier::complete_tx::bytes.b32 [%0], %1, [%2];"
                 :: "r"(dst), "r"(v), "r"(mbar) : "memory");
}
#define MBARRIER_INIT(mb, cnt) \
    asm volatile("mbarrier.init.shared.b64 [%0], %1;" :: "r"((uint32_t)(mb)), "r"((uint32_t)(cnt)) : "memory")
#define MBARRIER_ARRIVE_EXPECT_TX(mb, bytes) \
    asm volatile("mbarrier.arrive.expect_tx.shared.b64 _, [%0], %1;" \
        :: "r"((uint32_t)(mb)), "r"((uint32_t)(bytes)) : "memory")
#define MBAR_WAIT(mb, ph) do { \
    uint32_t _m = (uint32_t)(mb); uint32_t _p = (uint32_t)(ph); uint32_t _d; \
    asm volatile("{ .reg .pred p; mbarrier.try_wait.parity.acquire.cta.shared::cta.b64 p, [%1], %2; selp.b32 %0,1,0,p; }" \
        : "=r"(_d) : "r"(_m), "r"(_p) : "memory"); \
    if (!_d) { \
        asm volatile("{ .reg .pred P1;\nWL_%=:\n mbarrier.try_wait.parity.acquire.cta.shared::cta.b64 P1, [%0], %1, 0x989680;\n @P1 bra.uni WD_%=;\n bra.uni WL_%=;\nWD_%=:\n}" \
            :: "r"(_m), "r"(_p) : "memory"); \
    } \
} while (0)
#define CLUSTER_SYNC() do { \
    asm volatile("barrier.cluster.arrive.aligned;" ::: "memory"); \
    asm volatile("barrier.cluster.wait.aligned;" ::: "memory"); \
} while (0)

// fragment-order h layout: row = n*4 + (k&3), entry = k>>2, row stride 68 floats
#define HP_STR 68
#define HP_BUF (16 * HP_STR)      // floats per buffer
#define TXB1 4096u

// ---------------- weight transpose (stores tf32-rounded values) --------------
__global__ void k_transpose(const float* W0, const float* W1, const float* W2,
                            const float* W3, const float* W4, const float* W5) {
    int z = blockIdx.z;
    int tsr = z >> 2, g = z & 3;
    const float* W;
    switch (tsr) {
        case 0: W = W0; break; case 1: W = W1; break; case 2: W = W2; break;
        case 3: W = W3; break; case 4: W = W4; break; default: W = W5; break;
    }
    __shared__ float tile[32][33];
    int h0 = blockIdx.x * 32, d0 = blockIdx.y * 32;
    int tx = threadIdx.x, ty = threadIdx.y;
#pragma unroll
    for (int i = 0; i < 4; ++i) {
        int r = ty + i * 8;
        tile[r][tx] = W[(size_t)g * 65536 + (size_t)(d0 + r) * 256 + h0 + tx];
    }
    __syncthreads();
    float* out = &g_Wt[tsr][0][0];
#pragma unroll
    for (int i = 0; i < 4; ++i) {
        int r = ty + i * 8;
        out[(size_t)(g * 256 + h0 + r) * 256 + d0 + tx] =
            __uint_as_float(f2tf32(tile[tx][r]));
    }
}

// ---------------- tensor-core GEMM via mma.sync tf32 (unchanged) -------------
#define KS 36
__global__ void __launch_bounds__(256, 2) k_gemm_mma(
    const float* __restrict__ x,
    const float* __restrict__ bias0, const float* __restrict__ bias1,
    int layer)
{
    __shared__ uint32_t As[128 * KS];
    __shared__ uint32_t Bs[128 * KS];

    const int dir = blockIdx.z;
    const int m0 = blockIdx.y * 128, n0 = blockIdx.x * 128;
    const float* hsrc = &g_h1[dir][0][0][0];
    float* out = (layer == 1) ? &g_xp1[dir][0][0][0] : &g_xp2[dir][0][0][0];
    const float* bias = dir ? bias1 : bias0;
    const float* WtX = &g_Wt[(layer == 1) ? dir : 2 + dir][0][0];
    const float* WtH = &g_Wt[4 + dir][0][0];
    const int NC = (layer == 1) ? 8 : 16;

    const int tid = threadIdx.x, wid = tid >> 5, lane = tid & 31;
    const int wm = (wid >> 2) * 64;
    const int wn = (wid & 3) * 32;
    const int kq = lane & 3, rq = lane >> 2;

    float acc[4][4][4];
#pragma unroll
    for (int mf = 0; mf < 4; ++mf)
#pragma unroll
        for (int nf = 0; nf < 4; ++nf)
#pragma unroll
            for (int r = 0; r < 4; ++r) acc[mf][nf][r] = 0.f;

    const int lrow = tid >> 3;
    const int lk4  = (tid & 7) * 4;

    for (int c = 0; c < NC; ++c) {
        const bool isH = (c >= 8);
        const int kc = (c & 7) * 32;
        const float* Wt = isH ? WtH : WtX;

#pragma unroll
        for (int i = 0; i < 4; ++i) {
            int row = lrow + i * 32;
            int m = m0 + row, t = m >> 5, bb = m & 31;
            int tt = dir ? (Tz - 1 - t) : t;
            const float* ap = isH ? hsrc + ((size_t)tt * 32 + bb) * 256 + kc + lk4
                                  : x + ((size_t)bb * Tz + tt) * 256 + kc + lk4;
            float4 v = *(const float4*)ap;
            uint4 u = make_uint4(f2tf32(v.x), f2tf32(v.y), f2tf32(v.z), f2tf32(v.w));
            *(uint4*)&As[row * KS + lk4] = u;
        }
#pragma unroll
        for (int i = 0; i < 4; ++i) {
            int nr = lrow + i * 32;
            float4 v = *(const float4*)(Wt + (size_t)(n0 + nr) * 256 + kc + lk4);
            uint4 u = make_uint4(__float_as_uint(v.x), __float_as_uint(v.y),
                                 __float_as_uint(v.z), __float_as_uint(v.w));
            *(uint4*)&Bs[nr * KS + lk4] = u;
        }
        __syncthreads();

#pragma unroll
        for (int ks = 0; ks < 4; ++ks) {
            const int kk = ks * 8 + kq;
            uint32_t a[4][4], b[4][2];
#pragma unroll
            for (int mf = 0; mf < 4; ++mf) {
                int mi = wm + mf * 16 + rq;
                a[mf][0] = As[mi * KS + kk];
                a[mf][1] = As[(mi + 8) * KS + kk];
                a[mf][2] = As[mi * KS + kk + 4];
                a[mf][3] = As[(mi + 8) * KS + kk + 4];
            }
#pragma unroll
            for (int nf = 0; nf < 4; ++nf) {
                int ni = wn + nf * 8 + rq;
                b[nf][0] = Bs[ni * KS + kk];
                b[nf][1] = Bs[ni * KS + kk + 4];
            }
#pragma unroll
            for (int mf = 0; mf < 4; ++mf)
#pragma unroll
                for (int nf = 0; nf < 4; ++nf)
                    mma_tf32(acc[mf][nf], a[mf], b[nf]);
        }
        __syncthreads();
    }

#pragma unroll
    for (int nf = 0; nf < 4; ++nf) {
        int n = n0 + wn + nf * 8 + 2 * kq;
        float bx = 0.f, by = 0.f;
        if (layer == 1) { bx = bias[n]; by = bias[n + 1]; }
#pragma unroll
        for (int mf = 0; mf < 4; ++mf) {
            int m = m0 + wm + mf * 16 + rq;
            float2 v0 = make_float2(acc[mf][nf][0] + bx, acc[mf][nf][1] + by);
            float2 v1 = make_float2(acc[mf][nf][2] + bx, acc[mf][nf][3] + by);
            *(float2*)&out[(size_t)m * NG + n]       = v0;
            *(float2*)&out[(size_t)(m + 8) * NG + n] = v1;
        }
    }
}

// ---------------- layer1 recurrence: tensor core + fragment-order h ----------
// (round-10 structure; only transcendentals switched to MUFU)
__global__ void __launch_bounds__(256, 1) __cluster_dims__(8, 1, 1)
k_recur1(const float* __restrict__ Uf, const float* __restrict__ Ub)
{
    __shared__ __align__(16) uint32_t sHp[2 * HP_BUF];  // tf32 bits, frag order
    __shared__ float sGate[128 * 5];                    // [gc][b], stride 5
    __shared__ __align__(8) unsigned long long mb1[2];

    const int cid = blockIdx.x >> 3;
    const int dir = cid >> 3;
    const int bg  = cid & 7;
    const int r   = (int)cluster_rank();

    const float* U  = dir ? Ub : Uf;
    const float* xp = &g_xp1[dir][0][0][0];
    float* hs = &g_h1[dir][0][0][0];

    const uint32_t shp_base = smem_u32(&sHp[0]);
    const uint32_t mb_base  = smem_u32(&mb1[0]);

    const int tid = threadIdx.x, lane = tid & 31, w = tid >> 5;
    const int rq = lane >> 2, kq = lane & 3;

    // static A fragments: gc = w*16 + rq (+8), A[m][k] = U[g][k][r*32+hcol]
    const int gc0 = w * 16 + rq, gc1 = gc0 + 8;
    const int gg0 = gc0 >> 5, gg1 = gc1 >> 5;
    const int colu0 = r * 32 + (gc0 & 31), colu1 = r * 32 + (gc1 & 31);
    uint32_t ua[32][4];
#pragma unroll
    for (int kt = 0; kt < 32; ++kt) {
        int k0 = kt * 8 + kq;
        ua[kt][0] = f2tf32(U[(size_t)gg0 * 65536 + (size_t)k0 * 256 + colu0]);
        ua[kt][1] = f2tf32(U[(size_t)gg1 * 65536 + (size_t)k0 * 256 + colu1]);
        ua[kt][2] = f2tf32(U[(size_t)gg0 * 65536 + (size_t)(k0 + 4) * 256 + colu0]);
        ua[kt][3] = f2tf32(U[(size_t)gg1 * 65536 + (size_t)(k0 + 4) * 256 + colu1]);
    }

    for (int i = tid; i < 2 * HP_BUF; i += 256) sHp[i] = 0u;
    if (tid == 0) {
        MBARRIER_INIT(mb_base, 1);
        MBARRIER_INIT(mb_base + 8, 1);
        MBARRIER_ARRIVE_EXPECT_TX(mb_base, TXB1);
        MBARRIER_ARRIVE_EXPECT_TX(mb_base + 8, TXB1);
    }
    __syncthreads();
    CLUSTER_SYNC();

    const int cb = tid >> 5, chl = tid & 31;     // cell role (tid<128): batch=cb
    const int col = r * 32 + chl;
    const int bglob = bg * 4 + cb;
    const uint32_t hoff_cell = shp_base +
        (((cb * 4 + (col & 3)) * HP_STR + (col >> 2)) * 4);

    float c_state = 0.f;
    float xq[4] = {0.f, 0.f, 0.f, 0.f};
    if (tid < 128) {
        size_t xb = (size_t)bglob * NG + col;
        xq[0] = xp[xb]; xq[1] = xp[xb + 256]; xq[2] = xp[xb + 512]; xq[3] = xp[xb + 768];
    }
    int pp[2] = {0, 0};

    const uint4* hrow4_0 = (const uint4*)&sHp[((rq & 3) * 4 + kq) * HP_STR];
    const uint4* hrow4_1 = (const uint4*)&sHp[HP_BUF + ((rq & 3) * 4 + kq) * HP_STR];

    for (int t = 0; t < Tz; ++t) {
        float xn[4] = {0.f, 0.f, 0.f, 0.f};
        if (tid < 128 && t + 1 < Tz) {
            size_t xb = ((size_t)(t + 1) * 32 + bglob) * NG + col;
            xn[0] = xp[xb]; xn[1] = xp[xb + 256]; xn[2] = xp[xb + 512]; xn[3] = xp[xb + 768];
        }
        const int bs = t & 1;
        if (t > 0) {
            MBAR_WAIT(mb_base + bs * 8, pp[bs]);
            pp[bs] ^= 1;
        }
        if (t > 0 && tid == 0)
            MBARRIER_ARRIVE_EXPECT_TX(mb_base + bs * 8, TXB1);

        const uint4* hr = bs ? hrow4_1 : hrow4_0;
        float acc[4][4];
#pragma unroll
        for (int j = 0; j < 4; ++j)
#pragma unroll
            for (int q = 0; q < 4; ++q) acc[j][q] = 0.f;
#pragma unroll
        for (int j = 0; j < 16; ++j) {
            uint4 hv = hr[j];
            uint32_t b0[2] = {hv.x, hv.y};
            uint32_t b1[2] = {hv.z, hv.w};
            mma_tf32(acc[(2 * j) & 3], ua[2 * j], b0);
            mma_tf32(acc[(2 * j + 1) & 3], ua[2 * j + 1], b1);
        }
        float c0 = acc[0][0] + acc[1][0] + acc[2][0] + acc[3][0];
        float c1 = acc[0][1] + acc[1][1] + acc[2][1] + acc[3][1];
        float c2 = acc[0][2] + acc[1][2] + acc[2][2] + acc[3][2];
        float c3 = acc[0][3] + acc[1][3] + acc[2][3] + acc[3][3];
        if (kq < 2) {
            sGate[gc0 * 5 + 2 * kq]     = c0;
            sGate[gc0 * 5 + 2 * kq + 1] = c1;
            sGate[gc1 * 5 + 2 * kq]     = c2;
            sGate[gc1 * 5 + 2 * kq + 1] = c3;
        }
        __syncthreads();

        if (tid < 128) {
            float gi = fast_sigmoid(xq[0] + sGate[(0  + chl) * 5 + cb]);
            float gf = fast_sigmoid(xq[1] + sGate[(32 + chl) * 5 + cb]);
            float gg = fast_sigmoid(xq[2] + sGate[(64 + chl) * 5 + cb]);
            float go = fast_sigmoid(xq[3] + sGate[(96 + chl) * 5 + cb]);
            c_state = gf + c_state + gi * gg;
            float hn = go + fast_tanh(c_state);
            int tout = dir ? (Tz - 1 - t) : t;
            hs[((size_t)tout * 32 + bglob) * 256 + col] = hn;
            if (t + 1 < Tz) {
                uint32_t ht = f2tf32(hn);
                uint32_t ho = hoff_cell + (((t + 1) & 1) ? HP_BUF * 4 : 0);
                uint32_t mbn = mb_base + ((t + 1) & 1) * 8;
#pragma unroll
                for (int j = 0; j < 8; ++j)
                    st_async_u32(mapa_u32(ho, (uint32_t)j), ht, mapa_u32(mbn, (uint32_t)j));
                xq[0] = xn[0]; xq[1] = xn[1]; xq[2] = xn[2]; xq[3] = xn[3];
            }
        }
        __syncthreads();   // sGate reused next step
    }
    CLUSTER_SYNC();
}

// ---------------- layer2 recurrence: tensor core, U[0] only (round-10) -------
__global__ void __launch_bounds__(256, 1) __cluster_dims__(8, 1, 1)
k_recur2(const float* __restrict__ Uf, const float* __restrict__ Ub,
         const float* __restrict__ b2f, const float* __restrict__ b2b,
         float* __restrict__ dout)
{
    __shared__ __align__(16) uint32_t sHp2[2 * HP_BUF];
    __shared__ float sRedm[4][32][5];
    __shared__ __align__(8) unsigned long long mb2[2];

    const int cid = blockIdx.x >> 3;
    const int dir = cid >> 3;
    const int bg  = cid & 7;
    const int r   = (int)cluster_rank();

    const float* U  = dir ? Ub : Uf;      // only U[0] slice used
    const float* b2 = dir ? b2b : b2f;    // only b[0] used
    const float* xp = &g_xp2[dir][0][0][0];
    float* ynet = dout + (size_t)Bz * 512;
    float* yt   = dout;

    const uint32_t shp_base = smem_u32(&sHp2[0]);
    const uint32_t mb_base  = smem_u32(&mb2[0]);

    const int tid = threadIdx.x, lane = tid & 31, w = tid >> 5;
    const int rq = lane >> 2, kq = lane & 3;
    const int mt = w & 1, ksq = w >> 1;

    // static A fragments from U[0]: m = mt*16 + rq (+8), k = ksq*64 + kt*8 + kq (+4)
    const int cu0 = r * 32 + mt * 16 + rq, cu1 = cu0 + 8;
    uint32_t ua2[8][4];
#pragma unroll
    for (int kt = 0; kt < 8; ++kt) {
        int k0 = ksq * 64 + kt * 8 + kq;
        ua2[kt][0] = f2tf32(U[(size_t)k0 * 256 + cu0]);
        ua2[kt][1] = f2tf32(U[(size_t)k0 * 256 + cu1]);
        ua2[kt][2] = f2tf32(U[(size_t)(k0 + 4) * 256 + cu0]);
        ua2[kt][3] = f2tf32(U[(size_t)(k0 + 4) * 256 + cu1]);
    }

    for (int i = tid; i < 2 * HP_BUF; i += 256) sHp2[i] = 0u;
    if (tid == 0) {
        MBARRIER_INIT(mb_base, 1);
        MBARRIER_INIT(mb_base + 8, 1);
        MBARRIER_ARRIVE_EXPECT_TX(mb_base, TXB1);
        MBARRIER_ARRIVE_EXPECT_TX(mb_base + 8, TXB1);
    }
    __syncthreads();
    CLUSTER_SYNC();

    const int cb = tid >> 5, chl = tid & 31;
    const int col = r * 32 + chl;
    const int bglob = bg * 4 + cb;
    const float biasv = (tid < 128) ? b2[col] : 0.f;
    const uint32_t hoff_cell = shp_base +
        (((cb * 4 + (col & 3)) * HP_STR + (col >> 2)) * 4);

    float c_state = 0.f;
    float xq[4] = {0.f, 0.f, 0.f, 0.f};
    if (tid < 128) {
        size_t xb = (size_t)bglob * NG + col;
        xq[0] = xp[xb]; xq[1] = xp[xb + 256]; xq[2] = xp[xb + 512]; xq[3] = xp[xb + 768];
    }
    int pp[2] = {0, 0};

    // B source: row (rq&3)*4+kq, entries ksq*16 .. +16
    const uint4* hrow4_0 = (const uint4*)&sHp2[((rq & 3) * 4 + kq) * HP_STR + ksq * 16];
    const uint4* hrow4_1 = (const uint4*)&sHp2[HP_BUF + ((rq & 3) * 4 + kq) * HP_STR + ksq * 16];

    for (int t = 0; t < Tz; ++t) {
        float xn[4] = {0.f, 0.f, 0.f, 0.f};
        if (tid < 128 && t + 1 < Tz) {
            size_t xb = ((size_t)(t + 1) * 32 + bglob) * NG + col;
            xn[0] = xp[xb]; xn[1] = xp[xb + 256]; xn[2] = xp[xb + 512]; xn[3] = xp[xb + 768];
        }
        const int bs = t & 1;
        if (t > 0) {
            MBAR_WAIT(mb_base + bs * 8, pp[bs]);
            pp[bs] ^= 1;
        }
        if (t > 0 && tid == 0)
            MBARRIER_ARRIVE_EXPECT_TX(mb_base + bs * 8, TXB1);

        const uint4* hr = bs ? hrow4_1 : hrow4_0;
        float acc[2][4];
#pragma unroll
        for (int j = 0; j < 2; ++j)
#pragma unroll
            for (int q = 0; q < 4; ++q) acc[j][q] = 0.f;
#pragma unroll
        for (int j = 0; j < 4; ++j) {
            uint4 hv = hr[j];
            uint32_t b0[2] = {hv.x, hv.y};
            uint32_t b1[2] = {hv.z, hv.w};
            mma_tf32(acc[0], ua2[2 * j], b0);
            mma_tf32(acc[1], ua2[2 * j + 1], b1);
        }
        float c0 = acc[0][0] + acc[1][0];
        float c1 = acc[0][1] + acc[1][1];
        float c2 = acc[0][2] + acc[1][2];
        float c3 = acc[0][3] + acc[1][3];
        if (kq < 2) {
            sRedm[ksq][mt * 16 + rq][2 * kq]         = c0;
            sRedm[ksq][mt * 16 + rq][2 * kq + 1]     = c1;
            sRedm[ksq][mt * 16 + rq + 8][2 * kq]     = c2;
            sRedm[ksq][mt * 16 + rq + 8][2 * kq + 1] = c3;
        }
        __syncthreads();

        if (tid < 128) {
            float hu = biasv + sRedm[0][chl][cb] + sRedm[1][chl][cb]
                             + sRedm[2][chl][cb] + sRedm[3][chl][cb];
            float gi = fast_sigmoid(xq[0] + hu);
            float gf = fast_sigmoid(xq[1] + hu);
            float gg = fast_sigmoid(xq[2] + hu);
            float go = fast_sigmoid(xq[3] + hu);
            c_state = gf + c_state + gi * gg;
            float hn = go + fast_tanh(c_state);
            if (dir == 0)
                ynet[((size_t)bglob * Tz + t) * 512 + col] = hn;
            else
                ynet[((size_t)bglob * Tz + (Tz - 1 - t)) * 512 + 256 + col] = hn;
            if (t == Tz - 1)
                yt[(size_t)bglob * 512 + dir * 256 + col] = hn;
            if (t + 1 < Tz) {
                uint32_t ht = f2tf32(hn);
                uint32_t ho = hoff_cell + (((t + 1) & 1) ? HP_BUF * 4 : 0);
                uint32_t mbn = mb_base + ((t + 1) & 1) * 8;
#pragma unroll
                for (int j = 0; j < 8; ++j)
                    st_async_u32(mapa_u32(ho, (uint32_t)j), ht, mapa_u32(mbn, (uint32_t)j));
                xq[0] = xn[0]; xq[1] = xn[1]; xq[2] = xn[2]; xq[3] = xn[3];
            }
        }
        __syncthreads();   // sRedm reused next step
    }
    CLUSTER_SYNC();
}

// ---------------- launch ------------------------------------------------------
extern "C" void kernel_launch(void* const* d_in, const int* in_sizes, int n_in,
                              void* d_out, int out_size) {
    const float* x      = (const float*)d_in[0];
    const float* l1_W   = (const float*)d_in[1];
    const float* l1_U   = (const float*)d_in[2];
    const float* l1_b   = (const float*)d_in[3];
    const float* l1_Wb  = (const float*)d_in[4];
    const float* l1_Ub  = (const float*)d_in[5];
    const float* l1_bb  = (const float*)d_in[6];
    const float* l2_Wx  = (const float*)d_in[7];
    const float* l2_Wh  = (const float*)d_in[8];
    const float* l2_U   = (const float*)d_in[9];
    const float* l2_b   = (const float*)d_in[10];
    const float* l2_Wxb = (const float*)d_in[11];
    const float* l2_Whb = (const float*)d_in[12];
    const float* l2_Ub  = (const float*)d_in[13];
    const float* l2_bb  = (const float*)d_in[14];
    float* out = (float*)d_out;

    dim3 tg(8, 8, 24);
    k_transpose<<<tg, dim3(32, 8)>>>(l1_W, l1_Wb, l2_Wx, l2_Wxb, l2_Wh, l2_Whb);

    dim3 gg(8, 256, 2);   // n-tiles, m-tiles, dir
    k_gemm_mma<<<gg, 256>>>(x, l1_b, l1_bb, 1);
    k_recur1<<<128, 256>>>(l1_U, l1_Ub);
    k_gemm_mma<<<gg, 256>>>(x, nullptr, nullptr, 2);
    k_recur2<<<128, 256>>>(l2_U, l2_Ub, l2_b, l2_bb, out);
}

// round 13
// speedup vs baseline: 1.1253x; 1.0258x over previous
#include <cuda_runtime.h>
#include <math.h>
#include <stdint.h>

#define Bz 32
#define Tz 1024
#define Dz 256
#define Hz 256
#define NG 1024  // 4*H

// ---------------- scratch (device globals: no allocation allowed) ----------
__device__ __align__(16) float g_xp1[2][Tz][Bz][NG];   // layer1 gate preacts
__device__ __align__(16) float g_xp2[2][Tz][Bz][NG];   // layer2 gate preacts
__device__ __align__(16) float g_h1 [2][Tz][Bz][Hz];   // layer1 h (tf32 bits, orig-time)
__device__ __align__(16) float g_Wt[6][1024][256];     // transposed weights [n][k] (tf32)
__device__ __align__(16) uint32_t g_xt[Bz][Tz][Dz];    // x pre-rounded to tf32 bits

// ---------------- helpers ----------------------------------------------------
__device__ __forceinline__ float fast_tanh(float x) {
    float t;
    asm("tanh.approx.f32 %0, %1;" : "=f"(t) : "f"(x));
    return t;
}
__device__ __forceinline__ float fast_sigmoid(float x) {
    return fmaf(fast_tanh(0.5f * x), 0.5f, 0.5f);
}
__device__ __forceinline__ uint32_t f2tf32(float f) {
    uint32_t u;
    asm("cvt.rna.tf32.f32 %0, %1;" : "=r"(u) : "f"(f));
    return u;
}
__device__ __forceinline__ void mma_tf32(float* d, const uint32_t* a, const uint32_t* b) {
    asm volatile(
        "mma.sync.aligned.m16n8k8.row.col.f32.tf32.tf32.f32 "
        "{%0,%1,%2,%3}, {%4,%5,%6,%7}, {%8,%9}, {%0,%1,%2,%3};"
        : "+f"(d[0]), "+f"(d[1]), "+f"(d[2]), "+f"(d[3])
        : "r"(a[0]), "r"(a[1]), "r"(a[2]), "r"(a[3]), "r"(b[0]), "r"(b[1]));
}
__device__ __forceinline__ uint32_t smem_u32(const void* p) {
    uint32_t a;
    asm("{ .reg .u64 t; cvta.to.shared.u64 t, %1; cvt.u32.u64 %0, t; }" : "=r"(a) : "l"(p));
    return a;
}
__device__ __forceinline__ uint32_t cluster_rank() {
    uint32_t r;
    asm("mov.u32 %0, %%cluster_ctarank;" : "=r"(r));
    return r;
}
__device__ __forceinline__ uint32_t mapa_u32(uint32_t local, uint32_t rank) {
    uint32_t ra;
    asm("mapa.shared::cluster.u32 %0, %1, %2;" : "=r"(ra) : "r"(local), "r"(rank));
    return ra;
}
__device__ __forceinline__ void st_async_u32(uint32_t dst, uint32_t v, uint32_t mbar) {
    asm volatile("st.async.shared::cluster.mbarrier::complete_tx::bytes.b32 [%0], %1, [%2];"
                 :: "r"(dst), "r"(v), "r"(mbar) : "memory");
}
__device__ __forceinline__ void cp_async16(uint32_t saddr, const void* gaddr) {
    asm volatile("cp.async.cg.shared.global [%0], [%1], 16;" :: "r"(saddr), "l"(gaddr));
}
#define CP_COMMIT() asm volatile("cp.async.commit_group;" ::: "memory")
#define CP_WAIT1()  asm volatile("cp.async.wait_group 1;" ::: "memory")
#define CP_WAIT0()  asm volatile("cp.async.wait_group 0;" ::: "memory")
#define MBARRIER_INIT(mb, cnt) \
    asm volatile("mbarrier.init.shared.b64 [%0], %1;" :: "r"((uint32_t)(mb)), "r"((uint32_t)(cnt)) : "memory")
#define MBARRIER_ARRIVE_EXPECT_TX(mb, bytes) \
    asm volatile("mbarrier.arrive.expect_tx.shared.b64 _, [%0], %1;" \
        :: "r"((uint32_t)(mb)), "r"((uint32_t)(bytes)) : "memory")
#define MBAR_WAIT(mb, ph) do { \
    uint32_t _m = (uint32_t)(mb); uint32_t _p = (uint32_t)(ph); uint32_t _d; \
    asm volatile("{ .reg .pred p; mbarrier.try_wait.parity.acquire.cta.shared::cta.b64 p, [%1], %2; selp.b32 %0,1,0,p; }" \
        : "=r"(_d) : "r"(_m), "r"(_p) : "memory"); \
    if (!_d) { \
        asm volatile("{ .reg .pred P1;\nWL_%=:\n mbarrier.try_wait.parity.acquire.cta.shared::cta.b64 P1, [%0], %1, 0x989680;\n @P1 bra.uni WD_%=;\n bra.uni WL_%=;\nWD_%=:\n}" \
            :: "r"(_m), "r"(_p) : "memory"); \
    } \
} while (0)
#define CLUSTER_SYNC() do { \
    asm volatile("barrier.cluster.arrive.aligned;" ::: "memory"); \
    asm volatile("barrier.cluster.wait.aligned;" ::: "memory"); \
} while (0)

// fragment-order h layout: row = n*4 + (k&3), entry = k>>2, row stride 68 floats
#define HP_STR 68
#define HP_BUF (16 * HP_STR)
#define TXB1 4096u

// ---------------- x -> tf32 bits -----------------------------------------------
__global__ void k_cvt_x(const float* __restrict__ x) {
    size_t i = ((size_t)blockIdx.x * blockDim.x + threadIdx.x) * 4;
    float4 v = *(const float4*)(x + i);
    uint4 u = make_uint4(f2tf32(v.x), f2tf32(v.y), f2tf32(v.z), f2tf32(v.w));
    *(uint4*)(&g_xt[0][0][0] + i) = u;
}

// ---------------- weight transpose (stores tf32-rounded values) --------------
__global__ void k_transpose(const float* W0, const float* W1, const float* W2,
                            const float* W3, const float* W4, const float* W5) {
    int z = blockIdx.z;
    int tsr = z >> 2, g = z & 3;
    const float* W;
    switch (tsr) {
        case 0: W = W0; break; case 1: W = W1; break; case 2: W = W2; break;
        case 3: W = W3; break; case 4: W = W4; break; default: W = W5; break;
    }
    __shared__ float tile[32][33];
    int h0 = blockIdx.x * 32, d0 = blockIdx.y * 32;
    int tx = threadIdx.x, ty = threadIdx.y;
#pragma unroll
    for (int i = 0; i < 4; ++i) {
        int r = ty + i * 8;
        tile[r][tx] = W[(size_t)g * 65536 + (size_t)(d0 + r) * 256 + h0 + tx];
    }
    __syncthreads();
    float* out = &g_Wt[tsr][0][0];
#pragma unroll
    for (int i = 0; i < 4; ++i) {
        int r = ty + i * 8;
        out[(size_t)(g * 256 + h0 + r) * 256 + d0 + tx] =
            __uint_as_float(f2tf32(tile[tx][r]));
    }
}

// ---------------- tensor-core GEMM: cp.async double-buffered -----------------
#define KS 36
#define TILE_U (128 * KS)             // uint32 per matrix tile
// dynamic smem: [buf0 A][buf0 B][buf1 A][buf1 B]
#define GSMEM (4 * TILE_U * 4)
__global__ void __launch_bounds__(256, 2) k_gemm_mma(
    const float* __restrict__ bias0, const float* __restrict__ bias1,
    int layer)
{
    extern __shared__ __align__(16) uint32_t sm[];

    const int dir = blockIdx.z;
    const int m0 = blockIdx.y * 128, n0 = blockIdx.x * 128;
    const uint32_t* xsrc = &g_xt[0][0][0];
    const uint32_t* hsrc = (const uint32_t*)&g_h1[dir][0][0][0];
    float* out = (layer == 1) ? &g_xp1[dir][0][0][0] : &g_xp2[dir][0][0][0];
    const float* bias = dir ? bias1 : bias0;
    const uint32_t* WtX = (const uint32_t*)&g_Wt[(layer == 1) ? dir : 2 + dir][0][0];
    const uint32_t* WtH = (const uint32_t*)&g_Wt[4 + dir][0][0];
    const int NC = (layer == 1) ? 8 : 16;

    const int tid = threadIdx.x, wid = tid >> 5, lane = tid & 31;
    const int wm = (wid >> 2) * 64;
    const int wn = (wid & 3) * 32;
    const int kq = lane & 3, rq = lane >> 2;

    const int lrow = tid >> 3;
    const int lk4  = (tid & 7) * 4;
    const uint32_t smem_base = smem_u32(sm);

    // per-thread precomputed smem dst offsets (bytes)
    const uint32_t dstA = smem_base + (lrow * KS + lk4) * 4;
    const uint32_t dstB = smem_base + (TILE_U + lrow * KS + lk4) * 4;

    float acc[4][4][4];
#pragma unroll
    for (int mf = 0; mf < 4; ++mf)
#pragma unroll
        for (int nf = 0; nf < 4; ++nf)
#pragma unroll
            for (int r = 0; r < 4; ++r) acc[mf][nf][r] = 0.f;

    // chunk loader (cp.async, raw tf32 bits)
    auto load_chunk = [&](int c, int bb) {
        const bool isH = (c >= 8);
        const int kc = (c & 7) * 32;
        const uint32_t* Wt = isH ? WtH : WtX;
        const uint32_t boff = (uint32_t)(bb * 2 * TILE_U * 4);
#pragma unroll
        for (int i = 0; i < 4; ++i) {
            int row = lrow + i * 32;
            int m = m0 + row, t = m >> 5, bbb = m & 31;
            int tt = dir ? (Tz - 1 - t) : t;
            const uint32_t* ap = isH ? hsrc + ((size_t)tt * 32 + bbb) * 256 + kc + lk4
                                     : xsrc + ((size_t)bbb * Tz + tt) * 256 + kc + lk4;
            cp_async16(dstA + boff + (uint32_t)(i * 32 * KS * 4), ap);
        }
#pragma unroll
        for (int i = 0; i < 4; ++i) {
            int nr = lrow + i * 32;
            cp_async16(dstB + boff + (uint32_t)(i * 32 * KS * 4),
                       Wt + (size_t)(n0 + nr) * 256 + kc + lk4);
        }
    };

    load_chunk(0, 0);
    CP_COMMIT();

    for (int c = 0; c < NC; ++c) {
        if (c + 1 < NC) {
            load_chunk(c + 1, (c + 1) & 1);
            CP_COMMIT();
            CP_WAIT1();
        } else {
            CP_WAIT0();
        }
        __syncthreads();

        const uint32_t* As = sm + (c & 1) * 2 * TILE_U;
        const uint32_t* Bs = As + TILE_U;
#pragma unroll
        for (int ks = 0; ks < 4; ++ks) {
            const int kk = ks * 8 + kq;
            uint32_t a[4][4], b[4][2];
#pragma unroll
            for (int mf = 0; mf < 4; ++mf) {
                int mi = wm + mf * 16 + rq;
                a[mf][0] = As[mi * KS + kk];
                a[mf][1] = As[(mi + 8) * KS + kk];
                a[mf][2] = As[mi * KS + kk + 4];
                a[mf][3] = As[(mi + 8) * KS + kk + 4];
            }
#pragma unroll
            for (int nf = 0; nf < 4; ++nf) {
                int ni = wn + nf * 8 + rq;
                b[nf][0] = Bs[ni * KS + kk];
                b[nf][1] = Bs[ni * KS + kk + 4];
            }
#pragma unroll
            for (int mf = 0; mf < 4; ++mf)
#pragma unroll
                for (int nf = 0; nf < 4; ++nf)
                    mma_tf32(acc[mf][nf], a[mf], b[nf]);
        }
        __syncthreads();
    }

#pragma unroll
    for (int nf = 0; nf < 4; ++nf) {
        int n = n0 + wn + nf * 8 + 2 * kq;
        float bx = 0.f, by = 0.f;
        if (layer == 1) { bx = bias[n]; by = bias[n + 1]; }
#pragma unroll
        for (int mf = 0; mf < 4; ++mf) {
            int m = m0 + wm + mf * 16 + rq;
            float2 v0 = make_float2(acc[mf][nf][0] + bx, acc[mf][nf][1] + by);
            float2 v1 = make_float2(acc[mf][nf][2] + bx, acc[mf][nf][3] + by);
            *(float2*)&out[(size_t)m * NG + n]       = v0;
            *(float2*)&out[(size_t)(m + 8) * NG + n] = v1;
        }
    }
}

// ---------------- layer1 recurrence (round-12, hs stores tf32 bits) ----------
__global__ void __launch_bounds__(256, 1) __cluster_dims__(8, 1, 1)
k_recur1(const float* __restrict__ Uf, const float* __restrict__ Ub)
{
    __shared__ __align__(16) uint32_t sHp[2 * HP_BUF];
    __shared__ float sGate[128 * 5];
    __shared__ __align__(8) unsigned long long mb1[2];

    const int cid = blockIdx.x >> 3;
    const int dir = cid >> 3;
    const int bg  = cid & 7;
    const int r   = (int)cluster_rank();

    const float* U  = dir ? Ub : Uf;
    const float* xp = &g_xp1[dir][0][0][0];
    float* hs = &g_h1[dir][0][0][0];

    const uint32_t shp_base = smem_u32(&sHp[0]);
    const uint32_t mb_base  = smem_u32(&mb1[0]);

    const int tid = threadIdx.x, lane = tid & 31, w = tid >> 5;
    const int rq = lane >> 2, kq = lane & 3;

    const int gc0 = w * 16 + rq, gc1 = gc0 + 8;
    const int gg0 = gc0 >> 5, gg1 = gc1 >> 5;
    const int colu0 = r * 32 + (gc0 & 31), colu1 = r * 32 + (gc1 & 31);
    uint32_t ua[32][4];
#pragma unroll
    for (int kt = 0; kt < 32; ++kt) {
        int k0 = kt * 8 + kq;
        ua[kt][0] = f2tf32(U[(size_t)gg0 * 65536 + (size_t)k0 * 256 + colu0]);
        ua[kt][1] = f2tf32(U[(size_t)gg1 * 65536 + (size_t)k0 * 256 + colu1]);
        ua[kt][2] = f2tf32(U[(size_t)gg0 * 65536 + (size_t)(k0 + 4) * 256 + colu0]);
        ua[kt][3] = f2tf32(U[(size_t)gg1 * 65536 + (size_t)(k0 + 4) * 256 + colu1]);
    }

    for (int i = tid; i < 2 * HP_BUF; i += 256) sHp[i] = 0u;
    if (tid == 0) {
        MBARRIER_INIT(mb_base, 1);
        MBARRIER_INIT(mb_base + 8, 1);
        MBARRIER_ARRIVE_EXPECT_TX(mb_base, TXB1);
        MBARRIER_ARRIVE_EXPECT_TX(mb_base + 8, TXB1);
    }
    __syncthreads();
    CLUSTER_SYNC();

    const int cb = tid >> 5, chl = tid & 31;
    const int col = r * 32 + chl;
    const int bglob = bg * 4 + cb;
    const uint32_t hoff_cell = shp_base +
        (((cb * 4 + (col & 3)) * HP_STR + (col >> 2)) * 4);

    float c_state = 0.f;
    float xq[4] = {0.f, 0.f, 0.f, 0.f};
    if (tid < 128) {
        size_t xb = (size_t)bglob * NG + col;
        xq[0] = xp[xb]; xq[1] = xp[xb + 256]; xq[2] = xp[xb + 512]; xq[3] = xp[xb + 768];
    }
    int pp[2] = {0, 0};

    const uint4* hrow4_0 = (const uint4*)&sHp[((rq & 3) * 4 + kq) * HP_STR];
    const uint4* hrow4_1 = (const uint4*)&sHp[HP_BUF + ((rq & 3) * 4 + kq) * HP_STR];

    for (int t = 0; t < Tz; ++t) {
        float xn[4] = {0.f, 0.f, 0.f, 0.f};
        if (tid < 128 && t + 1 < Tz) {
            size_t xb = ((size_t)(t + 1) * 32 + bglob) * NG + col;
            xn[0] = xp[xb]; xn[1] = xp[xb + 256]; xn[2] = xp[xb + 512]; xn[3] = xp[xb + 768];
        }
        const int bs = t & 1;
        if (t > 0) {
            MBAR_WAIT(mb_base + bs * 8, pp[bs]);
            pp[bs] ^= 1;
        }
        if (t > 0 && tid == 0)
            MBARRIER_ARRIVE_EXPECT_TX(mb_base + bs * 8, TXB1);

        const uint4* hr = bs ? hrow4_1 : hrow4_0;
        float acc[4][4];
#pragma unroll
        for (int j = 0; j < 4; ++j)
#pragma unroll
            for (int q = 0; q < 4; ++q) acc[j][q] = 0.f;
#pragma unroll
        for (int j = 0; j < 16; ++j) {
            uint4 hv = hr[j];
            uint32_t b0[2] = {hv.x, hv.y};
            uint32_t b1[2] = {hv.z, hv.w};
            mma_tf32(acc[(2 * j) & 3], ua[2 * j], b0);
            mma_tf32(acc[(2 * j + 1) & 3], ua[2 * j + 1], b1);
        }
        float c0 = acc[0][0] + acc[1][0] + acc[2][0] + acc[3][0];
        float c1 = acc[0][1] + acc[1][1] + acc[2][1] + acc[3][1];
        float c2 = acc[0][2] + acc[1][2] + acc[2][2] + acc[3][2];
        float c3 = acc[0][3] + acc[1][3] + acc[2][3] + acc[3][3];
        if (kq < 2) {
            sGate[gc0 * 5 + 2 * kq]     = c0;
            sGate[gc0 * 5 + 2 * kq + 1] = c1;
            sGate[gc1 * 5 + 2 * kq]     = c2;
            sGate[gc1 * 5 + 2 * kq + 1] = c3;
        }
        __syncthreads();

        if (tid < 128) {
            float gi = fast_sigmoid(xq[0] + sGate[(0  + chl) * 5 + cb]);
            float gf = fast_sigmoid(xq[1] + sGate[(32 + chl) * 5 + cb]);
            float gg = fast_sigmoid(xq[2] + sGate[(64 + chl) * 5 + cb]);
            float go = fast_sigmoid(xq[3] + sGate[(96 + chl) * 5 + cb]);
            c_state = gf + c_state + gi * gg;
            float hn = go + fast_tanh(c_state);
            uint32_t ht = f2tf32(hn);
            int tout = dir ? (Tz - 1 - t) : t;
            // store tf32 bits: g_h1 is consumed only by GEMM2's A side
            hs[((size_t)tout * 32 + bglob) * 256 + col] = __uint_as_float(ht);
            if (t + 1 < Tz) {
                uint32_t ho = hoff_cell + (((t + 1) & 1) ? HP_BUF * 4 : 0);
                uint32_t mbn = mb_base + ((t + 1) & 1) * 8;
#pragma unroll
                for (int j = 0; j < 8; ++j)
                    st_async_u32(mapa_u32(ho, (uint32_t)j), ht, mapa_u32(mbn, (uint32_t)j));
                xq[0] = xn[0]; xq[1] = xn[1]; xq[2] = xn[2]; xq[3] = xn[3];
            }
        }
        __syncthreads();
    }
    CLUSTER_SYNC();
}

// ---------------- layer2 recurrence (round-12, unchanged) --------------------
__global__ void __launch_bounds__(256, 1) __cluster_dims__(8, 1, 1)
k_recur2(const float* __restrict__ Uf, const float* __restrict__ Ub,
         const float* __restrict__ b2f, const float* __restrict__ b2b,
         float* __restrict__ dout)
{
    __shared__ __align__(16) uint32_t sHp2[2 * HP_BUF];
    __shared__ float sRedm[4][32][5];
    __shared__ __align__(8) unsigned long long mb2[2];

    const int cid = blockIdx.x >> 3;
    const int dir = cid >> 3;
    const int bg  = cid & 7;
    const int r   = (int)cluster_rank();

    const float* U  = dir ? Ub : Uf;
    const float* b2 = dir ? b2b : b2f;
    const float* xp = &g_xp2[dir][0][0][0];
    float* ynet = dout + (size_t)Bz * 512;
    float* yt   = dout;

    const uint32_t shp_base = smem_u32(&sHp2[0]);
    const uint32_t mb_base  = smem_u32(&mb2[0]);

    const int tid = threadIdx.x, lane = tid & 31, w = tid >> 5;
    const int rq = lane >> 2, kq = lane & 3;
    const int mt = w & 1, ksq = w >> 1;

    const int cu0 = r * 32 + mt * 16 + rq, cu1 = cu0 + 8;
    uint32_t ua2[8][4];
#pragma unroll
    for (int kt = 0; kt < 8; ++kt) {
        int k0 = ksq * 64 + kt * 8 + kq;
        ua2[kt][0] = f2tf32(U[(size_t)k0 * 256 + cu0]);
        ua2[kt][1] = f2tf32(U[(size_t)k0 * 256 + cu1]);
        ua2[kt][2] = f2tf32(U[(size_t)(k0 + 4) * 256 + cu0]);
        ua2[kt][3] = f2tf32(U[(size_t)(k0 + 4) * 256 + cu1]);
    }

    for (int i = tid; i < 2 * HP_BUF; i += 256) sHp2[i] = 0u;
    if (tid == 0) {
        MBARRIER_INIT(mb_base, 1);
        MBARRIER_INIT(mb_base + 8, 1);
        MBARRIER_ARRIVE_EXPECT_TX(mb_base, TXB1);
        MBARRIER_ARRIVE_EXPECT_TX(mb_base + 8, TXB1);
    }
    __syncthreads();
    CLUSTER_SYNC();

    const int cb = tid >> 5, chl = tid & 31;
    const int col = r * 32 + chl;
    const int bglob = bg * 4 + cb;
    const float biasv = (tid < 128) ? b2[col] : 0.f;
    const uint32_t hoff_cell = shp_base +
        (((cb * 4 + (col & 3)) * HP_STR + (col >> 2)) * 4);

    float c_state = 0.f;
    float xq[4] = {0.f, 0.f, 0.f, 0.f};
    if (tid < 128) {
        size_t xb = (size_t)bglob * NG + col;
        xq[0] = xp[xb]; xq[1] = xp[xb + 256]; xq[2] = xp[xb + 512]; xq[3] = xp[xb + 768];
    }
    int pp[2] = {0, 0};

    const uint4* hrow4_0 = (const uint4*)&sHp2[((rq & 3) * 4 + kq) * HP_STR + ksq * 16];
    const uint4* hrow4_1 = (const uint4*)&sHp2[HP_BUF + ((rq & 3) * 4 + kq) * HP_STR + ksq * 16];

    for (int t = 0; t < Tz; ++t) {
        float xn[4] = {0.f, 0.f, 0.f, 0.f};
        if (tid < 128 && t + 1 < Tz) {
            size_t xb = ((size_t)(t + 1) * 32 + bglob) * NG + col;
            xn[0] = xp[xb]; xn[1] = xp[xb + 256]; xn[2] = xp[xb + 512]; xn[3] = xp[xb + 768];
        }
        const int bs = t & 1;
        if (t > 0) {
            MBAR_WAIT(mb_base + bs * 8, pp[bs]);
            pp[bs] ^= 1;
        }
        if (t > 0 && tid == 0)
            MBARRIER_ARRIVE_EXPECT_TX(mb_base + bs * 8, TXB1);

        const uint4* hr = bs ? hrow4_1 : hrow4_0;
        float acc[2][4];
#pragma unroll
        for (int j = 0; j < 2; ++j)
#pragma unroll
            for (int q = 0; q < 4; ++q) acc[j][q] = 0.f;
#pragma unroll
        for (int j = 0; j < 4; ++j) {
            uint4 hv = hr[j];
            uint32_t b0[2] = {hv.x, hv.y};
            uint32_t b1[2] = {hv.z, hv.w};
            mma_tf32(acc[0], ua2[2 * j], b0);
            mma_tf32(acc[1], ua2[2 * j + 1], b1);
        }
        float c0 = acc[0][0] + acc[1][0];
        float c1 = acc[0][1] + acc[1][1];
        float c2 = acc[0][2] + acc[1][2];
        float c3 = acc[0][3] + acc[1][3];
        if (kq < 2) {
            sRedm[ksq][mt * 16 + rq][2 * kq]         = c0;
            sRedm[ksq][mt * 16 + rq][2 * kq + 1]     = c1;
            sRedm[ksq][mt * 16 + rq + 8][2 * kq]     = c2;
            sRedm[ksq][mt * 16 + rq + 8][2 * kq + 1] = c3;
        }
        __syncthreads();

        if (tid < 128) {
            float hu = biasv + sRedm[0][chl][cb] + sRedm[1][chl][cb]
                             + sRedm[2][chl][cb] + sRedm[3][chl][cb];
            float gi = fast_sigmoid(xq[0] + hu);
            float gf = fast_sigmoid(xq[1] + hu);
            float gg = fast_sigmoid(xq[2] + hu);
            float go = fast_sigmoid(xq[3] + hu);
            c_state = gf + c_state + gi * gg;
            float hn = go + fast_tanh(c_state);
            if (dir == 0)
                ynet[((size_t)bglob * Tz + t) * 512 + col] = hn;
            else
                ynet[((size_t)bglob * Tz + (Tz - 1 - t)) * 512 + 256 + col] = hn;
            if (t == Tz - 1)
                yt[(size_t)bglob * 512 + dir * 256 + col] = hn;
            if (t + 1 < Tz) {
                uint32_t ht = f2tf32(hn);
                uint32_t ho = hoff_cell + (((t + 1) & 1) ? HP_BUF * 4 : 0);
                uint32_t mbn = mb_base + ((t + 1) & 1) * 8;
#pragma unroll
                for (int j = 0; j < 8; ++j)
                    st_async_u32(mapa_u32(ho, (uint32_t)j), ht, mapa_u32(mbn, (uint32_t)j));
                xq[0] = xn[0]; xq[1] = xn[1]; xq[2] = xn[2]; xq[3] = xn[3];
            }
        }
        __syncthreads();
    }
    CLUSTER_SYNC();
}

// ---------------- launch ------------------------------------------------------
extern "C" void kernel_launch(void* const* d_in, const int* in_sizes, int n_in,
                              void* d_out, int out_size) {
    const float* x      = (const float*)d_in[0];
    const float* l1_W   = (const float*)d_in[1];
    const float* l1_U   = (const float*)d_in[2];
    const float* l1_b   = (const float*)d_in[3];
    const float* l1_Wb  = (const float*)d_in[4];
    const float* l1_Ub  = (const float*)d_in[5];
    const float* l1_bb  = (const float*)d_in[6];
    const float* l2_Wx  = (const float*)d_in[7];
    const float* l2_Wh  = (const float*)d_in[8];
    const float* l2_U   = (const float*)d_in[9];
    const float* l2_b   = (const float*)d_in[10];
    const float* l2_Wxb = (const float*)d_in[11];
    const float* l2_Whb = (const float*)d_in[12];
    const float* l2_Ub  = (const float*)d_in[13];
    const float* l2_bb  = (const float*)d_in[14];
    float* out = (float*)d_out;

    static int smem_set = 0;
    if (!smem_set) {
        cudaFuncSetAttribute(k_gemm_mma, cudaFuncAttributeMaxDynamicSharedMemorySize, GSMEM);
        smem_set = 1;
    }

    k_cvt_x<<<(Bz * Tz * Dz) / (256 * 4), 256>>>(x);
    dim3 tg(8, 8, 24);
    k_transpose<<<tg, dim3(32, 8)>>>(l1_W, l1_Wb, l2_Wx, l2_Wxb, l2_Wh, l2_Whb);

    dim3 gg(8, 256, 2);   // n-tiles, m-tiles, dir
    k_gemm_mma<<<gg, 256, GSMEM>>>(l1_b, l1_bb, 1);
    k_recur1<<<128, 256>>>(l1_U, l1_Ub);
    k_gemm_mma<<<gg, 256, GSMEM>>>(nullptr, nullptr, 2);
    k_recur2<<<128, 256>>>(l2_U, l2_Ub, l2_b, l2_bb, out);
}